// round 1
// baseline (speedup 1.0000x reference)
#include <cuda_runtime.h>
#include <cstdint>
#include <math.h>

// ---------------- problem constants ----------------
#define NS    6400          // SAMPLE*SAMPLE patches per image
#define CCH   49            // PATCH*PATCH channels
#define IMGW  512
#define GW    169           // (512-7)/3 + 1 patch-grid size
#define EPSF  2.2204460492503131e-16f
#define LAMB  0.05f

// ---------------- device scratch (static; no runtime allocation) ----------------
__device__ int   g_base_t[NS];
__device__ int   g_base_r[NS];
__device__ float g_ymean[CCH];
__device__ float g_xf[CCH * NS];      // [c][p], channel-major
__device__ float g_yf[CCH * NS];
__device__ float g_d[(size_t)NS * NS];   // 163.84 MB distance matrix
__device__ unsigned long long g_amin[NS];
__device__ int   g_cnt[NS];
__device__ float g_rowloss[NS];

// ---------------- 1) grid-sample nearest indices ----------------
__global__ void k_idx(const float* __restrict__ tfield, const float* __restrict__ rfield) {
    int i = blockIdx.x * blockDim.x + threadIdx.x;
    if (i >= 2 * NS) return;
    const float* f = (i < NS) ? tfield : rfield;
    int p = (i < NS) ? i : (i - NS);
    // field = field01*2 - 1 ; ix = clip(round(((gx+1)*W - 1)*0.5)) ; half-even via rintf
    float gx = __fadd_rn(__fmul_rn(f[2 * p + 0], 2.0f), -1.0f);
    float gy = __fadd_rn(__fmul_rn(f[2 * p + 1], 2.0f), -1.0f);
    float fx = __fmul_rn(__fadd_rn(__fmul_rn(__fadd_rn(gx, 1.0f), (float)GW), -1.0f), 0.5f);
    float fy = __fmul_rn(__fadd_rn(__fmul_rn(__fadd_rn(gy, 1.0f), (float)GW), -1.0f), 0.5f);
    int ix = (int)rintf(fx); ix = ix < 0 ? 0 : (ix > GW - 1 ? GW - 1 : ix);
    int iy = (int)rintf(fy); iy = iy < 0 ? 0 : (iy > GW - 1 ? GW - 1 : iy);
    int base = (iy * 3) * IMGW + ix * 3;   // top-left of 7x7 patch in image
    if (i < NS) g_base_t[p] = base; else g_base_r[p] = base;
}

// ---------------- 2) refer patch channel mean (deterministic tree) ----------------
__global__ void k_mean(const float* __restrict__ rimg) {
    int c = blockIdx.x;                     // 49 blocks
    int off = (c / 7) * IMGW + (c % 7);
    int t = threadIdx.x;
    float s = 0.0f;
    for (int p = t; p < NS; p += 256) s += rimg[g_base_r[p] + off];
    __shared__ float sm[256];
    sm[t] = s; __syncthreads();
    for (int st = 128; st; st >>= 1) { if (t < st) sm[t] += sm[t + st]; __syncthreads(); }
    if (t == 0) g_ymean[c] = sm[0] * (1.0f / (float)NS);
}

// ---------------- 3) centered + L2-normalized feature vectors ----------------
__global__ void k_feat(const float* __restrict__ timg, const float* __restrict__ rimg) {
    int p = blockIdx.x * 256 + threadIdx.x;           // gridDim.x = 25
    bool is_t = (blockIdx.y == 0);
    const float* img = is_t ? timg : rimg;
    int base = is_t ? g_base_t[p] : g_base_r[p];
    float* out = is_t ? g_xf : g_yf;
    float v[CCH];
    float sq = 0.0f;
#pragma unroll
    for (int c = 0; c < CCH; c++) {
        v[c] = img[base + (c / 7) * IMGW + (c % 7)] - g_ymean[c];
        sq += v[c] * v[c];
    }
    float inv = 1.0f / (sqrtf(sq) + EPSF);
#pragma unroll
    for (int c = 0; c < CCH; c++) out[c * NS + p] = v[c] * inv;
}

// ---------------- 4) init argmin / counts ----------------
__global__ void k_init() {
    int p = blockIdx.x * 256 + threadIdx.x;
    if (p < NS) { g_amin[p] = ~0ull; g_cnt[p] = 0; }
}

// ---------------- 5) GEMM: d = max((1 - xf^T yf)/2, 0), store + row argmin ----------------
// tiles: 128 rows (p) x 64 cols (q), 256 threads, 8x4 micro-tile
__global__ void __launch_bounds__(256) k_gemm() {
    __shared__ float As[CCH][128];
    __shared__ float Bs[CCH][64];
    int by = blockIdx.y;   // 50 row tiles
    int bx = blockIdx.x;   // 100 col tiles
    int t = threadIdx.x;

    for (int i = t; i < CCH * 128; i += 256) {
        int k = i >> 7, m = i & 127;
        As[k][m] = g_xf[k * NS + by * 128 + m];
    }
    for (int i = t; i < CCH * 64; i += 256) {
        int k = i >> 6, m = i & 63;
        Bs[k][m] = g_yf[k * NS + bx * 64 + m];
    }
    __syncthreads();

    int tx = t & 15, ty = t >> 4;
    float acc[8][4];
#pragma unroll
    for (int i = 0; i < 8; i++)
#pragma unroll
        for (int j = 0; j < 4; j++) acc[i][j] = 0.0f;

#pragma unroll 1
    for (int k = 0; k < CCH; k++) {
        float4 b4 = *(const float4*)&Bs[k][tx * 4];
        float4 a0 = *(const float4*)&As[k][ty * 8];
        float4 a1 = *(const float4*)&As[k][ty * 8 + 4];
        float a[8] = {a0.x, a0.y, a0.z, a0.w, a1.x, a1.y, a1.z, a1.w};
        float b[4] = {b4.x, b4.y, b4.z, b4.w};
#pragma unroll
        for (int i = 0; i < 8; i++)
#pragma unroll
            for (int j = 0; j < 4; j++) acc[i][j] += a[i] * b[j];
    }

    int row0 = by * 128 + ty * 8;
    int col0 = bx * 64 + tx * 4;
#pragma unroll
    for (int i = 0; i < 8; i++) {
        float dv[4];
        unsigned long long key = ~0ull;
#pragma unroll
        for (int j = 0; j < 4; j++) {
            float sim = acc[i][j];
            float dd = fmaxf(__fmul_rn(__fadd_rn(1.0f, -sim), 0.5f), 0.0f);
            dv[j] = dd;
            unsigned long long kk =
                ((unsigned long long)__float_as_uint(dd) << 32) | (unsigned)(col0 + j);
            key = (kk < key) ? kk : key;   // strict <  -> first-index tie break
        }
        *(float4*)&g_d[(size_t)(row0 + i) * NS + col0] =
            make_float4(dv[0], dv[1], dv[2], dv[3]);
#pragma unroll
        for (int off = 8; off; off >>= 1) {
            unsigned long long o = __shfl_down_sync(0xffffffffu, key, off, 16);
            key = (o < key) ? o : key;
        }
        if (tx == 0) atomicMin(&g_amin[row0 + i], key);
    }
}

// ---------------- 6) occurrence counts ----------------
__global__ void k_cnt() {
    int p = blockIdx.x * 256 + threadIdx.x;
    if (p < NS) {
        unsigned q = (unsigned)(g_amin[p] & 0xffffffffu);
        atomicAdd(&g_cnt[q], 1);
    }
}

// ---------------- 7) per-row min + sum-exp -> row loss ----------------
__global__ void __launch_bounds__(256) k_row() {
    __shared__ float sd[NS];        // 25.6 KB: d' row cache
    __shared__ float sr[8];
    int p = blockIdx.x;
    int t = threadIdx.x;
    const float* drow = &g_d[(size_t)p * NS];

    for (int j = t; j < NS; j += 256)
        sd[j] = drow[j] + LAMB * (float)g_cnt[j];
    __syncthreads();

    // block min
    float m = 3.4e38f;
    for (int j = t; j < NS; j += 256) m = fminf(m, sd[j]);
#pragma unroll
    for (int o = 16; o; o >>= 1) m = fminf(m, __shfl_xor_sync(0xffffffffu, m, o));
    if ((t & 31) == 0) sr[t >> 5] = m;
    __syncthreads();
    if (t == 0) {
        float x = sr[0];
#pragma unroll
        for (int w = 1; w < 8; w++) x = fminf(x, sr[w]);
        sr[0] = x;
    }
    __syncthreads();
    m = sr[0];
    __syncthreads();

    float meps = __fadd_rn(m, EPSF);
    float inv = 1.0f / meps;

    // block sum of w = exp((1 - d'/(m+eps))*2)
    float s = 0.0f;
    for (int j = t; j < NS; j += 256) {
        float r = sd[j] * inv;
        s += __expf(__fmul_rn(__fadd_rn(1.0f, -r), 2.0f));
    }
#pragma unroll
    for (int o = 16; o; o >>= 1) s += __shfl_xor_sync(0xffffffffu, s, o);
    if ((t & 31) == 0) sr[t >> 5] = s;
    __syncthreads();
    if (t == 0) {
        float st = 0.0f;
#pragma unroll
        for (int w = 0; w < 8; w++) st += sr[w];
        float emax = __fmul_rn(__fadd_rn(1.0f, -__fmul_rn(m, inv)), 2.0f);
        // -log(CX) = log(sum w) - exponent_at_min
        g_rowloss[p] = logf(st) - emax;
    }
}

// ---------------- 8) final mean ----------------
__global__ void k_final(float* __restrict__ out) {
    int t = threadIdx.x;
    float s = 0.0f;
    for (int p = t; p < NS; p += 256) s += g_rowloss[p];
    __shared__ float sm[256];
    sm[t] = s; __syncthreads();
    for (int st = 128; st; st >>= 1) { if (t < st) sm[t] += sm[t + st]; __syncthreads(); }
    if (t == 0) out[0] = sm[0] * (1.0f / (float)NS);
}

// ---------------- host launch ----------------
extern "C" void kernel_launch(void* const* d_in, const int* in_sizes, int n_in,
                              void* d_out, int out_size) {
    (void)in_sizes; (void)n_in; (void)out_size;
    const float* timg   = (const float*)d_in[0];   // target_features [1,1,512,512]
    const float* rimg   = (const float*)d_in[1];   // refer_features  [1,1,512,512]
    const float* tfield = (const float*)d_in[2];   // target_field [1,80,80,2]
    const float* rfield = (const float*)d_in[3];   // refer_field  [1,80,80,2]
    float* out = (float*)d_out;

    k_idx  <<<50, 256>>>(tfield, rfield);
    k_mean <<<CCH, 256>>>(rimg);
    k_feat <<<dim3(25, 2), 256>>>(timg, rimg);
    k_init <<<25, 256>>>();
    k_gemm <<<dim3(100, 50), 256>>>();
    k_cnt  <<<25, 256>>>();
    k_row  <<<NS, 256>>>();
    k_final<<<1, 256>>>(out);
}